// round 5
// baseline (speedup 1.0000x reference)
#include <cuda_runtime.h>

// B=1, C=32, H=128, W=256, D=48 ; out [1,64,48,128,256] f32
#define HH 128
#define WW 256
#define CC 32
#define DD 48

constexpr int  HW      = HH * WW;          // 32768
constexpr long DHW     = (long)DD * HW;    // 1572864
constexpr int  XSTRIDE = 33;               // float2 per x-slot (pad: kills staging conflicts)
constexpr int  YCACHE  = WW * XSTRIDE;     // 8448 float2 = 67.6 KB
constexpr int  TSTRIDE = 33;               // transpose-staging row stride (floats)
constexpr int  NWARP   = 8;

__global__ __launch_bounds__(256, 2)
void cost_volume_kernel(const float* __restrict__ x,
                        const float* __restrict__ y,
                        const float* __restrict__ disp,
                        float* __restrict__ out)
{
    extern __shared__ float smem_raw[];
    float2* smY = (float2*)smem_raw;               // [256 x][33] {row0,row1} per channel slot
    float*  stg = smem_raw + 2 * YCACHE;           // [8 warps][32 w][33]

    const int h      = blockIdx.y;                 // 0..127
    const int dchunk = blockIdx.x;                 // 0..11 (4 d per block)
    const int tid    = threadIdx.x;
    const int warp   = tid >> 5;
    const int lane   = tid & 31;

    // iy depends only on h
    const float gy1  = (float)h / 63.5f;
    const float iy   = (gy1 * 128.0f - 1.0f) * 0.5f;
    const float y0f  = floorf(iy);
    const float wy   = iy - y0f;
    const float omwy = 1.0f - wy;
    const int   y0   = (int)y0f;
    const bool  vr0  = ((unsigned)y0       < (unsigned)HH);
    const bool  vr1  = ((unsigned)(y0 + 1) < (unsigned)HH);

    // Stage y rows: coalesced LDG (lanes -> consecutive xx), transposed STS into
    // channel-contiguous layout. Pad-33 => bank-pair (xx + c) mod 16: only 2-way.
    for (int i = tid; i < CC * WW; i += 256) {
        const int c  = i >> 8;    // 0..31
        const int xx = i & 255;   // 0..255
        const float* yp = y + (c * HH + y0) * WW + xx;
        const float v0 = vr0 ? __ldg(yp)      : 0.0f;
        const float v1 = vr1 ? __ldg(yp + WW) : 0.0f;
        smY[xx * XSTRIDE + c] = make_float2(v0, v1);
    }

    // Left half (pure broadcast of x over d) — no smem dependency, overlap with staging.
    {
        const int dloc = tid >> 6;           // 0..3
        const int d    = dchunk * 4 + dloc;
        const int w0   = (tid & 63) << 2;
        const float* xrow = x + h * WW + w0;
        float* outL = out + (long)d * HW + (long)h * WW + w0;
        #pragma unroll 8
        for (int c = 0; c < CC; ++c) {
            const float4 xv = __ldg((const float4*)(xrow + c * HW));
            *(float4*)(outL + (long)c * DHW) = xv;
        }
    }
    __syncthreads();

    float* mystg = stg + warp * (32 * TSTRIDE);

    // 32 warp-tiles per block (4 d x 8 w-blocks of 32); each warp does 4.
    #pragma unroll
    for (int t = 0; t < 4; ++t) {
        const int tileid = warp + t * NWARP;   // 0..31
        const int dloc   = tileid >> 3;        // 0..3
        const int wb     = tileid & 7;         // 0..7
        const int d      = dchunk * 4 + dloc;
        const int w0     = wb * 32;

        // 32 disparities for this tile, one per lane (coalesced)
        const float dreg = disp[(d * HH + h) * WW + w0 + lane];

        // Gather phase: lanes = channels -> conflict-free LDS by construction.
        #pragma unroll 4
        for (int p = 0; p < 32; ++p) {
            const float dval = __shfl_sync(0xffffffffu, dreg, p);
            const float cur  = (float)(w0 + p) - dval;
            const float ixv  = ((cur / 127.5f) * 256.0f - 1.0f) * 0.5f;
            const float x0f  = floorf(ixv);
            const float wx   = ixv - x0f;
            const int   x0i  = (int)x0f;
            const int   x1i  = x0i + 1;
            const float m0   = ((unsigned)x0i < (unsigned)WW) ? 1.0f : 0.0f;
            const float m1   = ((unsigned)x1i < (unsigned)WW) ? 1.0f : 0.0f;
            const int   xa   = min(max(x0i, 0), WW - 1);
            const int   xb   = min(max(x1i, 0), WW - 1);
            const float omwx = 1.0f - wx;
            const float w00 = omwx * omwy * m0;
            const float w01 = wx   * omwy * m1;
            const float w10 = omwx * wy   * m0;
            const float w11 = wx   * wy   * m1;

            const float2 pa = smY[xa * XSTRIDE + lane];   // 32 consecutive float2: 0-conflict
            const float2 pb = smY[xb * XSTRIDE + lane];
            const float o = pa.x * w00 + pb.x * w01 + pa.y * w10 + pb.y * w11;

            mystg[p * TSTRIDE + lane] = o;                // consecutive lanes: 0-conflict
        }
        __syncwarp();

        // Transposed readback + coalesced store: bank (lane + c) mod 32 -> 0-conflict
        float* outR = out + (long)CC * DHW + (long)d * HW + (long)h * WW + w0;
        #pragma unroll 8
        for (int c = 0; c < CC; ++c) {
            const float v = mystg[lane * TSTRIDE + c];
            outR[(long)c * DHW + lane] = v;               // 128B coalesced STG.32
        }
        __syncwarp();
    }
}

extern "C" void kernel_launch(void* const* d_in, const int* in_sizes, int n_in,
                              void* d_out, int out_size)
{
    const float* x    = (const float*)d_in[0];
    const float* y    = (const float*)d_in[1];
    const float* disp = (const float*)d_in[2];
    float* out = (float*)d_out;

    const int smem_bytes = (2 * YCACHE + NWARP * 32 * TSTRIDE) * (int)sizeof(float); // ~101 KB
    cudaFuncSetAttribute(cost_volume_kernel,
                         cudaFuncAttributeMaxDynamicSharedMemorySize, smem_bytes);

    dim3 grid(DD / 4, HH);   // (12, 128) = 1536 blocks
    cost_volume_kernel<<<grid, 256, smem_bytes>>>(x, y, disp, out);
}